// round 13
// baseline (speedup 1.0000x reference)
#include <cuda_runtime.h>
#include <cuda_bf16.h>
#include <math.h>
#include <cstdint>

// Problem constants
#define BB 2
#define TT 2048
#define CC 1024
#define HH 16
#define DD 64
#define MM (BB*TT)   // 4096

// ---------------------------------------------------------------------------
// Scratch (allocation-free: __device__ globals)
// ---------------------------------------------------------------------------
__device__ float g_q[MM*CC];
__device__ float g_k[MM*CC];
__device__ float g_v[MM*CC];
__device__ float g_att[MM*CC];
// tf32-pre-rounded operands (rounded ONCE; GEMMs then feed raw bits)
__device__ float g_xt[MM*CC];
__device__ float g_wqt[CC*CC];
__device__ float g_wkt[CC*CC];
__device__ float g_wvt[CC*CC];
__device__ float g_wot[CC*CC];

// ---------------------------------------------------------------------------
// mma.sync helpers (sm_100 base target: HMMA path, no tcgen05)
// ---------------------------------------------------------------------------
__device__ __forceinline__ uint32_t f2tf(float f) {
    uint32_t u;
    asm("cvt.rna.tf32.f32 %0, %1;" : "=r"(u) : "f"(f));
    return u;
}

__device__ __forceinline__ void mma_tf32(float* d, const uint32_t* a, const uint32_t* b) {
    asm volatile(
        "mma.sync.aligned.m16n8k8.row.col.f32.tf32.tf32.f32 "
        "{%0,%1,%2,%3}, {%4,%5,%6,%7}, {%8,%9}, {%0,%1,%2,%3};"
        : "+f"(d[0]), "+f"(d[1]), "+f"(d[2]), "+f"(d[3])
        : "r"(a[0]), "r"(a[1]), "r"(a[2]), "r"(a[3]),
          "r"(b[0]), "r"(b[1]));
}

// ldmatrix: four 8x8 b16 tiles == four 8(row)x4(fp32) tiles.
__device__ __forceinline__ void ldsm_x4(uint32_t& r0, uint32_t& r1,
                                        uint32_t& r2, uint32_t& r3,
                                        uint32_t addr) {
    asm volatile(
        "ldmatrix.sync.aligned.m8n8.x4.shared.b16 {%0,%1,%2,%3}, [%4];"
        : "=r"(r0), "=r"(r1), "=r"(r2), "=r"(r3) : "r"(addr));
}

__device__ __forceinline__ uint32_t smem_u32(const void* p) {
    uint32_t a;
    asm("{ .reg .u64 t; cvta.to.shared.u64 t, %1; cvt.u32.u64 %0, t; }"
        : "=r"(a) : "l"(p));
    return a;
}

__device__ __forceinline__ void cp_async16(uint32_t dst, const void* src) {
    asm volatile("cp.async.ca.shared.global [%0], [%1], 16;" :: "r"(dst), "l"(src));
}

__device__ __forceinline__ void cp_async16_cg(uint32_t dst, const void* src) {
    asm volatile("cp.async.cg.shared.global [%0], [%1], 16;" :: "r"(dst), "l"(src));
}

// ===========================================================================
// Prepass: round fp32 -> tf32-rounded fp32 (low 13 mantissa bits zero), once.
// ===========================================================================
__global__ __launch_bounds__(256) void tf32_round_kernel(
    const float4* __restrict__ src, float4* __restrict__ dst, int n4)
{
    int i = blockIdx.x * blockDim.x + threadIdx.x;
    if (i < n4) {
        float4 v = src[i];
        float4 o;
        o.x = __uint_as_float(f2tf(v.x));
        o.y = __uint_as_float(f2tf(v.y));
        o.z = __uint_as_float(f2tf(v.z));
        o.w = __uint_as_float(f2tf(v.w));
        dst[i] = o;
    }
}

// ===========================================================================
// tf32 mma.sync GEMM core:  C[M,N] = A[M,K] @ W[N,K]^T + bias[N]
// Inputs A and W are PRE-ROUNDED to tf32 (prepass) -> no cvt in inner loop;
// HW truncation of pre-rounded values is the identity (bit-identical math).
// CTA tile 128x128, BK=16, 256 threads = 8 warps (2M x 4N), warp tile 64x32.
// 4-stage cp.async ring, k-loop unrolled by 4 (constant stage indices).
// Fragment loads via ldmatrix.x4 (LDSM).
// ===========================================================================
#define GBK 16
#define BKP 20
#define NKT (CC / GBK)      // 64  (divisible by 4)
#define GSTG 4
#define STG_U32 (128 * BKP)                        // uint32 per array per stage
#define GEMM_SMEM_BYTES (GSTG * 2 * STG_U32 * 4)   // 81920

__device__ __forceinline__ void gemm_mma_body(
    const float* __restrict__ A, const float* __restrict__ W,
    const float* __restrict__ bias, float* __restrict__ C,
    int m0, int n0, uint32_t* sm)
{
    const int tid = threadIdx.x;
    const int wid = tid >> 5;
    const int lane = tid & 31;
    const int g  = lane >> 2;
    const int tg = lane & 3;
    const int warp_m = wid >> 2;
    const int warp_n = wid & 3;
    const float* Ag = A + (size_t)m0 * CC;
    const float* Wg = W + (size_t)n0 * CC;

    const uint32_t sbase = smem_u32(sm);

    // ldmatrix per-lane row/col selectors
    const int arow = (lane & 7) + ((lane >> 3) & 1) * 8;
    const int acol = (lane >> 4) * 4;
    const int brow = (lane & 7) + ((lane >> 4) & 1) * 8;
    const int bcol = ((lane >> 3) & 1) * 4;

    uint32_t aLd[GSTG], bLd[GSTG];
    #pragma unroll
    for (int s = 0; s < GSTG; s++) {
        aLd[s] = sbase + (uint32_t)(s * STG_U32) * 4u
               + (uint32_t)(((warp_m * 64 + arow) * BKP + acol) * 4);
        bLd[s] = sbase + (uint32_t)((GSTG + s) * STG_U32) * 4u
               + (uint32_t)(((warp_n * 32 + brow) * BKP + bcol) * 4);
    }

    float d[4][4][4];
    #pragma unroll
    for (int mt = 0; mt < 4; mt++)
        #pragma unroll
        for (int nt = 0; nt < 4; nt++)
            #pragma unroll
            for (int r = 0; r < 4; r++) d[mt][nt][r] = 0.f;

    const int r0 = tid >> 2;          // 0..63 : rows r0 and r0+64
    const int c0 = (tid & 3) * 4;     // 0,4,8,12
    const uint32_t so0 = (uint32_t)(r0 * BKP + c0) * 4u;
    const uint32_t so1 = (uint32_t)((r0 + 64) * BKP + c0) * 4u;

    // preload tiles 0,1,2 into stages 0,1,2 (one commit group each)
    #pragma unroll
    for (int p = 0; p < 3; p++) {
        const int koff = p * GBK;
        const uint32_t aB = sbase + (uint32_t)(p * STG_U32) * 4u;
        const uint32_t wB = sbase + (uint32_t)((GSTG + p) * STG_U32) * 4u;
        cp_async16_cg(aB + so0, Ag + (size_t)r0 * CC + koff + c0);
        cp_async16_cg(aB + so1, Ag + (size_t)(r0 + 64) * CC + koff + c0);
        cp_async16_cg(wB + so0, Wg + (size_t)r0 * CC + koff + c0);
        cp_async16_cg(wB + so1, Wg + (size_t)(r0 + 64) * CC + koff + c0);
        asm volatile("cp.async.commit_group;");
    }

    for (int kt = 0; kt < NKT; kt += GSTG) {
        #pragma unroll
        for (int u = 0; u < GSTG; u++) {
            // oldest outstanding group (tile kt+u) complete
            asm volatile("cp.async.wait_group 2;");
            __syncthreads();   // stage u visible; readers of stage (u+3)&3 done

            const int pf = kt + u + 3;
            if (pf < NKT) {
                const int ps = (u + 3) & 3;          // compile-time constant
                const int koff = pf * GBK;
                const uint32_t aB = sbase + (uint32_t)(ps * STG_U32) * 4u;
                const uint32_t wB = sbase + (uint32_t)((GSTG + ps) * STG_U32) * 4u;
                cp_async16_cg(aB + so0, Ag + (size_t)r0 * CC + koff + c0);
                cp_async16_cg(aB + so1, Ag + (size_t)(r0 + 64) * CC + koff + c0);
                cp_async16_cg(wB + so0, Wg + (size_t)r0 * CC + koff + c0);
                cp_async16_cg(wB + so1, Wg + (size_t)(r0 + 64) * CC + koff + c0);
            }
            asm volatile("cp.async.commit_group;");  // uniform group count

            const uint32_t aB = aLd[u];              // constant index
            const uint32_t bB = bLd[u];
            #pragma unroll
            for (int ks = 0; ks < 2; ks++) {
                uint32_t af[4][4], bf[2][4];
                #pragma unroll
                for (int mt = 0; mt < 4; mt++) {
                    ldsm_x4(af[mt][0], af[mt][1], af[mt][2], af[mt][3],
                            aB + (uint32_t)((mt * 16 * BKP + ks * 8) * 4));
                }
                #pragma unroll
                for (int np = 0; np < 2; np++) {
                    ldsm_x4(bf[np][0], bf[np][1], bf[np][2], bf[np][3],
                            bB + (uint32_t)((np * 16 * BKP + ks * 8) * 4));
                }
                // operands are pre-rounded tf32 -> no cvt needed
                #pragma unroll
                for (int mt = 0; mt < 4; mt++)
                    #pragma unroll
                    for (int nt = 0; nt < 4; nt++)
                        mma_tf32(d[mt][nt], af[mt], &bf[nt >> 1][(nt & 1) * 2]);
            }
        }
    }

    #pragma unroll
    for (int mt = 0; mt < 4; mt++) {
        const int row = m0 + warp_m * 64 + mt * 16 + g;
        #pragma unroll
        for (int nt = 0; nt < 4; nt++) {
            const int col = n0 + warp_n * 32 + nt * 8 + tg * 2;
            float2 bv = *reinterpret_cast<const float2*>(bias + col);
            float2 o0 = make_float2(d[mt][nt][0] + bv.x, d[mt][nt][1] + bv.y);
            float2 o1 = make_float2(d[mt][nt][2] + bv.x, d[mt][nt][3] + bv.y);
            *reinterpret_cast<float2*>(C + (size_t)row * CC + col) = o0;
            *reinterpret_cast<float2*>(C + (size_t)(row + 8) * CC + col) = o1;
        }
    }
}

// Single-matrix GEMM (output projection)
__global__ __launch_bounds__(256) void gemm_mma_kernel(
    const float* __restrict__ A, const float* __restrict__ W,
    const float* __restrict__ bias, float* __restrict__ C)
{
    extern __shared__ __align__(16) uint32_t smg[];
    gemm_mma_body(A, W, bias, C, blockIdx.y * 128, blockIdx.x * 128, smg);
}

// Fused QKV projection: blockIdx.z selects {Wq,bq,q} / {Wk,bk,k} / {Wv,bv,v}
__global__ __launch_bounds__(256) void gemm_qkv_kernel(
    const float* __restrict__ x,
    const float* __restrict__ Wq, const float* __restrict__ bq, float* __restrict__ q,
    const float* __restrict__ Wk, const float* __restrict__ bk, float* __restrict__ k,
    const float* __restrict__ Wv, const float* __restrict__ bv, float* __restrict__ v)
{
    extern __shared__ __align__(16) uint32_t smg[];
    const float* W; const float* b; float* C;
    if (blockIdx.z == 0)      { W = Wq; b = bq; C = q; }
    else if (blockIdx.z == 1) { W = Wk; b = bk; C = k; }
    else                      { W = Wv; b = bv; C = v; }
    gemm_mma_body(x, W, b, C, blockIdx.y * 128, blockIdx.x * 128, smg);
}

// ===========================================================================
// Tensor-core flash attention (causal), tf32 mma.sync.
// CTA: 128 q rows, 8 warps (16 q rows/warp), kv tile 64, D=64.
// grid = (T/128, H, B) = (16, 16, 2), 256 threads.
// K fragments via ldmatrix.x4; V scalar. Output written tf32-PRE-ROUNDED so
// the out-projection GEMM needs no cvt (identical numerics to cvt-in-GEMM).
// qt REVERSED vs blockIdx.x so heaviest blocks schedule first.
// ===========================================================================
#define AQ 128
#define AKV 64
#define KP 68               // K/Q smem row pad (floats): conflict-free
#define VP 72               // V   smem row pad (floats): conflict-free
#define SM_K0 0
#define SM_K1 (64*KP)
#define SM_V0 (2*64*KP)
#define SM_V1 (2*64*KP + 64*VP)
#define ATT_SMEM_BYTES ((2*64*KP + 2*64*VP) * 4)   // 71680

__global__ __launch_bounds__(256, 2) void attention_mma_kernel(
    const float* __restrict__ Qg, const float* __restrict__ Kg,
    const float* __restrict__ Vg, float* __restrict__ Og)
{
    extern __shared__ __align__(16) float smf[];
    const uint32_t sbase = smem_u32(smf);
    const int tid = threadIdx.x;
    const int w = tid >> 5;
    const int lane = tid & 31;
    const int g = lane >> 2, tg = lane & 3;
    const int qt = gridDim.x - 1 - blockIdx.x;   // heavy blocks first
    const int h = blockIdx.y, b = blockIdx.z;
    const int q0 = qt * AQ;
    const size_t bh = (size_t)b * TT * CC + (size_t)h * DD;  // + t*CC + d

    // --- stage Q (scaled by 1/sqrt(D)) into smem [128][KP] ---
    {
        const float sc = 0.125f;
        #pragma unroll
        for (int j = 0; j < 8; j++) {
            int idx = tid + j * 256;           // 0..2047
            int r = idx >> 4, cc = (idx & 15) * 4;
            float4 val = *reinterpret_cast<const float4*>(
                Qg + bh + (size_t)(q0 + r) * CC + cc);
            float* dst = smf + r * KP + cc;
            dst[0] = val.x * sc; dst[1] = val.y * sc;
            dst[2] = val.z * sc; dst[3] = val.w * sc;
        }
    }
    __syncthreads();

    // --- Q A-fragments to registers (persist whole kernel) ---
    uint32_t qa[8][4];
    {
        const uint32_t* Qs = reinterpret_cast<const uint32_t*>(smf);
        const int r0 = (w * 16 + g) * KP;
        #pragma unroll
        for (int kk = 0; kk < 8; kk++) {
            qa[kk][0] = Qs[r0 + kk * 8 + tg];
            qa[kk][1] = Qs[r0 + 8 * KP + kk * 8 + tg];
            qa[kk][2] = Qs[r0 + kk * 8 + tg + 4];
            qa[kk][3] = Qs[r0 + 8 * KP + kk * 8 + tg + 4];
        }
    }
    __syncthreads();   // Q stage area becomes K buffers

    float s[8][4], oo[8][4];
    float m0 = -1e30f, m1 = -1e30f, l0 = 0.f, l1 = 0.f;
    #pragma unroll
    for (int nt = 0; nt < 8; nt++) {
        oo[nt][0] = oo[nt][1] = oo[nt][2] = oo[nt][3] = 0.f;
    }

    const int ntiles = 2 * qt + 2;
    const int wrow_first = q0 + w * 16;
    const int wrow_last  = wrow_first + 15;

    const uint32_t kbuf_b[2] = { sbase + SM_K0 * 4u, sbase + SM_K1 * 4u };
    const uint32_t vbuf_b[2] = { sbase + SM_V0 * 4u, sbase + SM_V1 * 4u };

    // K ldmatrix per-lane selectors
    const int krow = lane & 7;
    const int kcol = (lane >> 3) * 4;
    const uint32_t kLd[2] = {
        kbuf_b[0] + (uint32_t)((krow * KP + kcol) * 4),
        kbuf_b[1] + (uint32_t)((krow * KP + kcol) * 4)
    };

    // preload tile 0
    #pragma unroll
    for (int j = 0; j < 4; j++) {
        int idx = tid + j * 256;               // 0..1023
        int r = idx >> 4, cc = (idx & 15) * 4;
        const float* srcK = Kg + bh + (size_t)r * CC + cc;
        const float* srcV = Vg + bh + (size_t)r * CC + cc;
        cp_async16(kbuf_b[0] + (uint32_t)(r * KP + cc) * 4u, srcK);
        cp_async16(vbuf_b[0] + (uint32_t)(r * VP + cc) * 4u, srcV);
    }
    asm volatile("cp.async.commit_group;");
    asm volatile("cp.async.wait_group 0;");
    __syncthreads();

    for (int t = 0; t < ntiles; t++) {
        const int buf = t & 1;
        if (t + 1 < ntiles) {
            const int kv0n = (t + 1) * AKV;
            #pragma unroll
            for (int j = 0; j < 4; j++) {
                int idx = tid + j * 256;
                int r = idx >> 4, cc = (idx & 15) * 4;
                const float* srcK = Kg + bh + (size_t)(kv0n + r) * CC + cc;
                const float* srcV = Vg + bh + (size_t)(kv0n + r) * CC + cc;
                cp_async16(kbuf_b[buf ^ 1] + (uint32_t)(r * KP + cc) * 4u, srcK);
                cp_async16(vbuf_b[buf ^ 1] + (uint32_t)(r * VP + cc) * 4u, srcV);
            }
            asm volatile("cp.async.commit_group;");
        }

        const int kv0 = t * AKV;
        if (kv0 <= wrow_last) {   // warp has at least one unmasked element
            const uint32_t kB = kLd[buf];
            const uint32_t* Vs = reinterpret_cast<const uint32_t*>(smf)
                                 + (buf ? SM_V1 : SM_V0);
            // ---- S = Q K^T (K fragments via ldmatrix.x4) ----
            #pragma unroll
            for (int nt = 0; nt < 8; nt++) {
                s[nt][0] = s[nt][1] = s[nt][2] = s[nt][3] = 0.f;
            }
            #pragma unroll
            for (int nt = 0; nt < 8; nt++) {
                #pragma unroll
                for (int kkp = 0; kkp < 4; kkp++) {
                    uint32_t kb[4];
                    ldsm_x4(kb[0], kb[1], kb[2], kb[3],
                            kB + (uint32_t)((nt * 8 * KP + kkp * 16) * 4));
                    mma_tf32(s[nt], qa[2 * kkp],     &kb[0]);
                    mma_tf32(s[nt], qa[2 * kkp + 1], &kb[2]);
                }
            }
            // ---- causal mask (diagonal tiles only) ----
            if (kv0 + AKV - 1 > wrow_first) {
                const int r0a = wrow_first + g, r1a = r0a + 8;
                #pragma unroll
                for (int nt = 0; nt < 8; nt++) {
                    const int c = kv0 + nt * 8 + 2 * tg;
                    if (c     > r0a) s[nt][0] = -1e30f;
                    if (c + 1 > r0a) s[nt][1] = -1e30f;
                    if (c     > r1a) s[nt][2] = -1e30f;
                    if (c + 1 > r1a) s[nt][3] = -1e30f;
                }
            }
            // ---- online softmax (register-resident) ----
            float mx0 = m0, mx1 = m1;
            #pragma unroll
            for (int nt = 0; nt < 8; nt++) {
                mx0 = fmaxf(mx0, fmaxf(s[nt][0], s[nt][1]));
                mx1 = fmaxf(mx1, fmaxf(s[nt][2], s[nt][3]));
            }
            mx0 = fmaxf(mx0, __shfl_xor_sync(0xffffffffu, mx0, 1));
            mx0 = fmaxf(mx0, __shfl_xor_sync(0xffffffffu, mx0, 2));
            mx1 = fmaxf(mx1, __shfl_xor_sync(0xffffffffu, mx1, 1));
            mx1 = fmaxf(mx1, __shfl_xor_sync(0xffffffffu, mx1, 2));
            const float al0 = __expf(m0 - mx0), al1 = __expf(m1 - mx1);
            m0 = mx0; m1 = mx1;
            float sum0 = 0.f, sum1 = 0.f;
            #pragma unroll
            for (int nt = 0; nt < 8; nt++) {
                s[nt][0] = __expf(s[nt][0] - mx0); sum0 += s[nt][0];
                s[nt][1] = __expf(s[nt][1] - mx0); sum0 += s[nt][1];
                s[nt][2] = __expf(s[nt][2] - mx1); sum1 += s[nt][2];
                s[nt][3] = __expf(s[nt][3] - mx1); sum1 += s[nt][3];
            }
            l0 = l0 * al0 + sum0;
            l1 = l1 * al1 + sum1;
            #pragma unroll
            for (int nt = 0; nt < 8; nt++) {
                oo[nt][0] *= al0; oo[nt][1] *= al0;
                oo[nt][2] *= al1; oo[nt][3] *= al1;
            }
            // ---- P (C-frag) -> A-frag via shuffles, in place ----
            const int base = lane & ~3;
            #pragma unroll
            for (int kk = 0; kk < 8; kk++) {
                const int srcA = base | (tg >> 1);
                const int srcB = srcA + 2;
                float x0 = __shfl_sync(0xffffffffu, s[kk][0], srcA);
                float x1 = __shfl_sync(0xffffffffu, s[kk][1], srcA);
                float x2 = __shfl_sync(0xffffffffu, s[kk][2], srcA);
                float x3 = __shfl_sync(0xffffffffu, s[kk][3], srcA);
                float y0 = __shfl_sync(0xffffffffu, s[kk][0], srcB);
                float y1 = __shfl_sync(0xffffffffu, s[kk][1], srcB);
                float y2 = __shfl_sync(0xffffffffu, s[kk][2], srcB);
                float y3 = __shfl_sync(0xffffffffu, s[kk][3], srcB);
                const bool odd = tg & 1;
                s[kk][0] = odd ? x1 : x0;   // a0: row g,   col tg
                s[kk][1] = odd ? x3 : x2;   // a1: row g+8, col tg
                s[kk][2] = odd ? y1 : y0;   // a2: row g,   col tg+4
                s[kk][3] = odd ? y3 : y2;   // a3: row g+8, col tg+4
            }
            // ---- O += P V ----
            #pragma unroll
            for (int nt = 0; nt < 8; nt++) {
                #pragma unroll
                for (int kk = 0; kk < 8; kk++) {
                    uint32_t bb[2] = { Vs[(kk * 8 + tg) * VP + nt * 8 + g],
                                       Vs[(kk * 8 + tg + 4) * VP + nt * 8 + g] };
                    mma_tf32(oo[nt], reinterpret_cast<uint32_t*>(s[kk]), bb);
                }
            }
        }
        if (t + 1 < ntiles) asm volatile("cp.async.wait_group 0;");
        __syncthreads();
    }

    // ---- finalize: reduce l over the quad, normalize, store tf32-rounded ----
    l0 += __shfl_xor_sync(0xffffffffu, l0, 1);
    l0 += __shfl_xor_sync(0xffffffffu, l0, 2);
    l1 += __shfl_xor_sync(0xffffffffu, l1, 1);
    l1 += __shfl_xor_sync(0xffffffffu, l1, 2);
    const float inv0 = 1.f / l0, inv1 = 1.f / l1;
    const int r0a = q0 + w * 16 + g, r1a = r0a + 8;
    #pragma unroll
    for (int nt = 0; nt < 8; nt++) {
        const int c = nt * 8 + 2 * tg;
        *reinterpret_cast<float2*>(Og + bh + (size_t)r0a * CC + c) =
            make_float2(__uint_as_float(f2tf(oo[nt][0] * inv0)),
                        __uint_as_float(f2tf(oo[nt][1] * inv0)));
        *reinterpret_cast<float2*>(Og + bh + (size_t)r1a * CC + c) =
            make_float2(__uint_as_float(f2tf(oo[nt][2] * inv1)),
                        __uint_as_float(f2tf(oo[nt][3] * inv1)));
    }
}

// ---------------------------------------------------------------------------
// Launch
// ---------------------------------------------------------------------------
extern "C" void kernel_launch(void* const* d_in, const int* in_sizes, int n_in,
                              void* d_out, int out_size)
{
    const float* x  = (const float*)d_in[0];
    const float* Wq = (const float*)d_in[1];
    const float* bq = (const float*)d_in[2];
    const float* Wk = (const float*)d_in[3];
    const float* bk = (const float*)d_in[4];
    const float* Wv = (const float*)d_in[5];
    const float* bv = (const float*)d_in[6];
    const float* Wo = (const float*)d_in[7];
    const float* bo = (const float*)d_in[8];
    float* out = (float*)d_out;

    float *qp, *kp, *vp, *ap;
    float *xt, *wqt, *wkt, *wvt, *wot;
    cudaGetSymbolAddress((void**)&qp, g_q);
    cudaGetSymbolAddress((void**)&kp, g_k);
    cudaGetSymbolAddress((void**)&vp, g_v);
    cudaGetSymbolAddress((void**)&ap, g_att);
    cudaGetSymbolAddress((void**)&xt, g_xt);
    cudaGetSymbolAddress((void**)&wqt, g_wqt);
    cudaGetSymbolAddress((void**)&wkt, g_wkt);
    cudaGetSymbolAddress((void**)&wvt, g_wvt);
    cudaGetSymbolAddress((void**)&wot, g_wot);

    cudaFuncSetAttribute(gemm_qkv_kernel,
                         cudaFuncAttributeMaxDynamicSharedMemorySize,
                         GEMM_SMEM_BYTES);
    cudaFuncSetAttribute(gemm_mma_kernel,
                         cudaFuncAttributeMaxDynamicSharedMemorySize,
                         GEMM_SMEM_BYTES);

    // Prepass: tf32-round x and weights once
    const int nx4 = MM * CC / 4;   // 1M float4
    const int nw4 = CC * CC / 4;   // 256K float4
    tf32_round_kernel<<<(nx4 + 255) / 256, 256>>>(
        (const float4*)x, (float4*)xt, nx4);
    tf32_round_kernel<<<(nw4 + 255) / 256, 256>>>(
        (const float4*)Wq, (float4*)wqt, nw4);
    tf32_round_kernel<<<(nw4 + 255) / 256, 256>>>(
        (const float4*)Wk, (float4*)wkt, nw4);
    tf32_round_kernel<<<(nw4 + 255) / 256, 256>>>(
        (const float4*)Wv, (float4*)wvt, nw4);
    tf32_round_kernel<<<(nw4 + 255) / 256, 256>>>(
        (const float4*)Wo, (float4*)wot, nw4);

    // Fused QKV projection: one launch, 768 CTAs
    gemm_qkv_kernel<<<dim3(CC / 128, MM / 128, 3), 256, GEMM_SMEM_BYTES>>>(
        xt, wqt, bq, qp, wkt, bk, kp, wvt, bv, vp);

    cudaFuncSetAttribute(attention_mma_kernel,
                         cudaFuncAttributeMaxDynamicSharedMemorySize,
                         ATT_SMEM_BYTES);
    attention_mma_kernel<<<dim3(TT / AQ, HH, BB), 256, ATT_SMEM_BYTES>>>(
        qp, kp, vp, ap);

    gemm_mma_kernel<<<dim3(CC / 128, MM / 128), 256, GEMM_SMEM_BYTES>>>(
        ap, wot, bo, out);
}

// round 14
// speedup vs baseline: 1.0100x; 1.0100x over previous
#include <cuda_runtime.h>
#include <cuda_bf16.h>
#include <math.h>
#include <cstdint>

// Problem constants
#define BB 2
#define TT 2048
#define CC 1024
#define HH 16
#define DD 64
#define MM (BB*TT)   // 4096

// ---------------------------------------------------------------------------
// Scratch (allocation-free: __device__ globals)
// g_v holds V TRANSPOSED: v_t[b][h][d][t]
// ---------------------------------------------------------------------------
__device__ float g_q[MM*CC];
__device__ float g_k[MM*CC];
__device__ float g_v[MM*CC];
__device__ float g_att[MM*CC];

// ---------------------------------------------------------------------------
// mma.sync helpers (sm_100 base target: HMMA path, no tcgen05)
// ---------------------------------------------------------------------------
__device__ __forceinline__ uint32_t f2tf_u(uint32_t x) {
    uint32_t u;
    asm("cvt.rna.tf32.f32 %0, %1;" : "=r"(u) : "f"(__uint_as_float(x)));
    return u;
}

__device__ __forceinline__ void mma_tf32(float* d, const uint32_t* a, const uint32_t* b) {
    asm volatile(
        "mma.sync.aligned.m16n8k8.row.col.f32.tf32.tf32.f32 "
        "{%0,%1,%2,%3}, {%4,%5,%6,%7}, {%8,%9}, {%0,%1,%2,%3};"
        : "+f"(d[0]), "+f"(d[1]), "+f"(d[2]), "+f"(d[3])
        : "r"(a[0]), "r"(a[1]), "r"(a[2]), "r"(a[3]),
          "r"(b[0]), "r"(b[1]));
}

// ldmatrix: four 8x8 b16 tiles == four 8(row)x4(fp32) tiles.
__device__ __forceinline__ void ldsm_x4(uint32_t& r0, uint32_t& r1,
                                        uint32_t& r2, uint32_t& r3,
                                        uint32_t addr) {
    asm volatile(
        "ldmatrix.sync.aligned.m8n8.x4.shared.b16 {%0,%1,%2,%3}, [%4];"
        : "=r"(r0), "=r"(r1), "=r"(r2), "=r"(r3) : "r"(addr));
}

__device__ __forceinline__ uint32_t smem_u32(const void* p) {
    uint32_t a;
    asm("{ .reg .u64 t; cvta.to.shared.u64 t, %1; cvt.u32.u64 %0, t; }"
        : "=r"(a) : "l"(p));
    return a;
}

__device__ __forceinline__ void cp_async16(uint32_t dst, const void* src) {
    asm volatile("cp.async.ca.shared.global [%0], [%1], 16;" :: "r"(dst), "l"(src));
}

__device__ __forceinline__ void cp_async16_cg(uint32_t dst, const void* src) {
    asm volatile("cp.async.cg.shared.global [%0], [%1], 16;" :: "r"(dst), "l"(src));
}

// ===========================================================================
// tf32 mma.sync GEMM core:  C[M,N] = A[M,K] @ W[N,K]^T + bias[N]
// CTA tile 128x128, BK=16, 256 threads = 8 warps (2M x 4N), warp tile 64x32.
// 4-stage cp.async ring, k-loop unrolled by 4 (constant stage indices).
// Fragment loads via ldmatrix.x4 (LDSM); cvt.rna.tf32 at fragment load.
// vtrans: epilogue writes TRANSPOSED to v_t[b][h][d][t] via smem (for V proj).
// ===========================================================================
#define GBK 16
#define BKP 20
#define NKT (CC / GBK)      // 64  (divisible by 4)
#define GSTG 4
#define STG_U32 (128 * BKP)                        // uint32 per array per stage
#define GEMM_SMEM_BYTES (GSTG * 2 * STG_U32 * 4)   // 81920
#define PADT 132            // transpose buffer row stride (floats)

__device__ __forceinline__ void gemm_mma_body(
    const float* __restrict__ A, const float* __restrict__ W,
    const float* __restrict__ bias, float* __restrict__ C,
    int m0, int n0, uint32_t* sm, int vtrans)
{
    const int tid = threadIdx.x;
    const int wid = tid >> 5;
    const int lane = tid & 31;
    const int g  = lane >> 2;
    const int tg = lane & 3;
    const int warp_m = wid >> 2;
    const int warp_n = wid & 3;
    const float* Ag = A + (size_t)m0 * CC;
    const float* Wg = W + (size_t)n0 * CC;

    const uint32_t sbase = smem_u32(sm);

    // ldmatrix per-lane row/col selectors
    const int arow = (lane & 7) + ((lane >> 3) & 1) * 8;
    const int acol = (lane >> 4) * 4;
    const int brow = (lane & 7) + ((lane >> 4) & 1) * 8;
    const int bcol = ((lane >> 3) & 1) * 4;

    uint32_t aLd[GSTG], bLd[GSTG];
    #pragma unroll
    for (int s = 0; s < GSTG; s++) {
        aLd[s] = sbase + (uint32_t)(s * STG_U32) * 4u
               + (uint32_t)(((warp_m * 64 + arow) * BKP + acol) * 4);
        bLd[s] = sbase + (uint32_t)((GSTG + s) * STG_U32) * 4u
               + (uint32_t)(((warp_n * 32 + brow) * BKP + bcol) * 4);
    }

    float d[4][4][4];
    #pragma unroll
    for (int mt = 0; mt < 4; mt++)
        #pragma unroll
        for (int nt = 0; nt < 4; nt++)
            #pragma unroll
            for (int r = 0; r < 4; r++) d[mt][nt][r] = 0.f;

    const int r0 = tid >> 2;          // 0..63 : rows r0 and r0+64
    const int c0 = (tid & 3) * 4;     // 0,4,8,12
    const uint32_t so0 = (uint32_t)(r0 * BKP + c0) * 4u;
    const uint32_t so1 = (uint32_t)((r0 + 64) * BKP + c0) * 4u;

    // preload tiles 0,1,2 into stages 0,1,2 (one commit group each)
    #pragma unroll
    for (int p = 0; p < 3; p++) {
        const int koff = p * GBK;
        const uint32_t aB = sbase + (uint32_t)(p * STG_U32) * 4u;
        const uint32_t wB = sbase + (uint32_t)((GSTG + p) * STG_U32) * 4u;
        cp_async16_cg(aB + so0, Ag + (size_t)r0 * CC + koff + c0);
        cp_async16_cg(aB + so1, Ag + (size_t)(r0 + 64) * CC + koff + c0);
        cp_async16_cg(wB + so0, Wg + (size_t)r0 * CC + koff + c0);
        cp_async16_cg(wB + so1, Wg + (size_t)(r0 + 64) * CC + koff + c0);
        asm volatile("cp.async.commit_group;");
    }

    for (int kt = 0; kt < NKT; kt += GSTG) {
        #pragma unroll
        for (int u = 0; u < GSTG; u++) {
            asm volatile("cp.async.wait_group 2;");
            __syncthreads();

            const int pf = kt + u + 3;
            if (pf < NKT) {
                const int ps = (u + 3) & 3;          // compile-time constant
                const int koff = pf * GBK;
                const uint32_t aB = sbase + (uint32_t)(ps * STG_U32) * 4u;
                const uint32_t wB = sbase + (uint32_t)((GSTG + ps) * STG_U32) * 4u;
                cp_async16_cg(aB + so0, Ag + (size_t)r0 * CC + koff + c0);
                cp_async16_cg(aB + so1, Ag + (size_t)(r0 + 64) * CC + koff + c0);
                cp_async16_cg(wB + so0, Wg + (size_t)r0 * CC + koff + c0);
                cp_async16_cg(wB + so1, Wg + (size_t)(r0 + 64) * CC + koff + c0);
            }
            asm volatile("cp.async.commit_group;");  // uniform group count

            const uint32_t aB = aLd[u];              // constant index
            const uint32_t bB = bLd[u];
            #pragma unroll
            for (int ks = 0; ks < 2; ks++) {
                uint32_t af[4][4], bf[2][4];
                #pragma unroll
                for (int mt = 0; mt < 4; mt++) {
                    ldsm_x4(af[mt][0], af[mt][1], af[mt][2], af[mt][3],
                            aB + (uint32_t)((mt * 16 * BKP + ks * 8) * 4));
                }
                #pragma unroll
                for (int np = 0; np < 2; np++) {
                    ldsm_x4(bf[np][0], bf[np][1], bf[np][2], bf[np][3],
                            bB + (uint32_t)((np * 16 * BKP + ks * 8) * 4));
                }
                #pragma unroll
                for (int mt = 0; mt < 4; mt++)
                    #pragma unroll
                    for (int i = 0; i < 4; i++)
                        af[mt][i] = f2tf_u(af[mt][i]);
                #pragma unroll
                for (int np = 0; np < 2; np++)
                    #pragma unroll
                    for (int i = 0; i < 4; i++)
                        bf[np][i] = f2tf_u(bf[np][i]);
                #pragma unroll
                for (int mt = 0; mt < 4; mt++)
                    #pragma unroll
                    for (int nt = 0; nt < 4; nt++)
                        mma_tf32(d[mt][nt], af[mt], &bf[nt >> 1][(nt & 1) * 2]);
            }
        }
    }

    if (!vtrans) {
        #pragma unroll
        for (int mt = 0; mt < 4; mt++) {
            const int row = m0 + warp_m * 64 + mt * 16 + g;
            #pragma unroll
            for (int nt = 0; nt < 4; nt++) {
                const int col = n0 + warp_n * 32 + nt * 8 + tg * 2;
                float2 bv = *reinterpret_cast<const float2*>(bias + col);
                float2 o0 = make_float2(d[mt][nt][0] + bv.x, d[mt][nt][1] + bv.y);
                float2 o1 = make_float2(d[mt][nt][2] + bv.x, d[mt][nt][3] + bv.y);
                *reinterpret_cast<float2*>(C + (size_t)row * CC + col) = o0;
                *reinterpret_cast<float2*>(C + (size_t)(row + 8) * CC + col) = o1;
            }
        }
    } else {
        // Transposed epilogue: C-tile (128 t-rows x 128 c-cols) -> smem S[c][t]
        // (conflict-free: banks 8tg+g), then coalesced float4 stores to
        // v_t[b][h][d][t].  Stage smem is dead (last tile consumed above).
        float* S = reinterpret_cast<float*>(sm);
        __syncthreads();
        #pragma unroll
        for (int mt = 0; mt < 4; mt++) {
            const int row = warp_m * 64 + mt * 16 + g;
            #pragma unroll
            for (int nt = 0; nt < 4; nt++) {
                const int col = warp_n * 32 + nt * 8 + tg * 2;
                const float b0 = bias[n0 + col];
                const float b1 = bias[n0 + col + 1];
                S[(col)     * PADT + row]     = d[mt][nt][0] + b0;
                S[(col + 1) * PADT + row]     = d[mt][nt][1] + b1;
                S[(col)     * PADT + row + 8] = d[mt][nt][2] + b0;
                S[(col + 1) * PADT + row + 8] = d[mt][nt][3] + b1;
            }
        }
        __syncthreads();
        const int bb = m0 >> 11;          // batch index (m0 multiple of 128)
        const int t0 = m0 & (TT - 1);
        #pragma unroll
        for (int j = 0; j < 16; j++) {
            const int idx = tid + j * 256;       // 0..4095
            const int c  = idx >> 5;             // 0..127 (tile col)
            const int t4 = (idx & 31) * 4;       // 0..124 (tile row, x4)
            float4 v4 = *reinterpret_cast<float4*>(&S[c * PADT + t4]);
            const int cg = n0 + c;
            const int hh = cg >> 6, dd2 = cg & 63;
            float* dst = C + (((size_t)bb * HH + hh) * DD + dd2) * TT + t0 + t4;
            *reinterpret_cast<float4*>(dst) = v4;
        }
    }
}

// Single-matrix GEMM (output projection)
__global__ __launch_bounds__(256) void gemm_mma_kernel(
    const float* __restrict__ A, const float* __restrict__ W,
    const float* __restrict__ bias, float* __restrict__ C)
{
    extern __shared__ __align__(16) uint32_t smg[];
    gemm_mma_body(A, W, bias, C, blockIdx.y * 128, blockIdx.x * 128, smg, 0);
}

// Fused QKV projection: blockIdx.z selects {Wq,bq,q} / {Wk,bk,k} / {Wv,bv,v_t}
__global__ __launch_bounds__(256) void gemm_qkv_kernel(
    const float* __restrict__ x,
    const float* __restrict__ Wq, const float* __restrict__ bq, float* __restrict__ q,
    const float* __restrict__ Wk, const float* __restrict__ bk, float* __restrict__ k,
    const float* __restrict__ Wv, const float* __restrict__ bv, float* __restrict__ v)
{
    extern __shared__ __align__(16) uint32_t smg[];
    const float* W; const float* b; float* C; int vt;
    if (blockIdx.z == 0)      { W = Wq; b = bq; C = q; vt = 0; }
    else if (blockIdx.z == 1) { W = Wk; b = bk; C = k; vt = 0; }
    else                      { W = Wv; b = bv; C = v; vt = 1; }
    gemm_mma_body(x, W, b, C, blockIdx.y * 128, blockIdx.x * 128, smg, vt);
}

// ===========================================================================
// Tensor-core flash attention (causal), tf32 mma.sync.
// CTA: 128 q rows, 8 warps (16 q rows/warp), kv tile 64, D=64.
// grid = (T/128, H, B) = (16, 16, 2), 256 threads.
// K AND V fragments via ldmatrix.x4 (V is pre-transposed: v_t[b][h][d][t]).
// qt REVERSED vs blockIdx.x so heaviest blocks schedule first.
// ===========================================================================
#define AQ 128
#define AKV 64
#define KP 68               // K/Q/V smem row pad (floats): conflict-free
#define SM_K0 0
#define SM_K1 (64*KP)
#define SM_V0 (2*64*KP)
#define SM_V1 (3*64*KP)
#define ATT_SMEM_BYTES (4*64*KP*4)   // 69632

__global__ __launch_bounds__(256, 2) void attention_mma_kernel(
    const float* __restrict__ Qg, const float* __restrict__ Kg,
    const float* __restrict__ Vt, float* __restrict__ Og)
{
    extern __shared__ __align__(16) float smf[];
    const uint32_t sbase = smem_u32(smf);
    const int tid = threadIdx.x;
    const int w = tid >> 5;
    const int lane = tid & 31;
    const int g = lane >> 2, tg = lane & 3;
    const int qt = gridDim.x - 1 - blockIdx.x;   // heavy blocks first
    const int h = blockIdx.y, b = blockIdx.z;
    const int q0 = qt * AQ;
    const size_t bh  = (size_t)b * TT * CC + (size_t)h * DD;       // Q/K/O base
    const float* vtp = Vt + ((size_t)b * HH + h) * (size_t)DD * TT; // V^T base

    // --- stage Q (scaled by 1/sqrt(D)) into smem [128][KP] ---
    {
        const float sc = 0.125f;
        #pragma unroll
        for (int j = 0; j < 8; j++) {
            int idx = tid + j * 256;           // 0..2047
            int r = idx >> 4, cc = (idx & 15) * 4;
            float4 val = *reinterpret_cast<const float4*>(
                Qg + bh + (size_t)(q0 + r) * CC + cc);
            float* dst = smf + r * KP + cc;
            dst[0] = val.x * sc; dst[1] = val.y * sc;
            dst[2] = val.z * sc; dst[3] = val.w * sc;
        }
    }
    __syncthreads();

    // --- Q A-fragments to registers (persist whole kernel) ---
    uint32_t qa[8][4];
    {
        const uint32_t* Qs = reinterpret_cast<const uint32_t*>(smf);
        const int r0 = (w * 16 + g) * KP;
        #pragma unroll
        for (int kk = 0; kk < 8; kk++) {
            qa[kk][0] = Qs[r0 + kk * 8 + tg];
            qa[kk][1] = Qs[r0 + 8 * KP + kk * 8 + tg];
            qa[kk][2] = Qs[r0 + kk * 8 + tg + 4];
            qa[kk][3] = Qs[r0 + 8 * KP + kk * 8 + tg + 4];
        }
    }
    __syncthreads();   // Q stage area becomes K buffers

    float s[8][4], oo[8][4];
    float m0 = -1e30f, m1 = -1e30f, l0 = 0.f, l1 = 0.f;
    #pragma unroll
    for (int nt = 0; nt < 8; nt++) {
        oo[nt][0] = oo[nt][1] = oo[nt][2] = oo[nt][3] = 0.f;
    }

    const int ntiles = 2 * qt + 2;
    const int wrow_first = q0 + w * 16;
    const int wrow_last  = wrow_first + 15;

    const uint32_t kbuf_b[2] = { sbase + SM_K0 * 4u, sbase + SM_K1 * 4u };
    const uint32_t vbuf_b[2] = { sbase + SM_V0 * 4u, sbase + SM_V1 * 4u };

    // ldmatrix per-lane selectors (same pattern for K and V^T)
    const int lrow = lane & 7;
    const int lcol = (lane >> 3) * 4;
    const uint32_t loff = (uint32_t)((lrow * KP + lcol) * 4);
    const uint32_t kLd[2] = { kbuf_b[0] + loff, kbuf_b[1] + loff };
    const uint32_t vLd[2] = { vbuf_b[0] + loff, vbuf_b[1] + loff };

    // preload tile 0: K rows = kv, V^T rows = d (both 64x64, KP pad)
    #pragma unroll
    for (int j = 0; j < 4; j++) {
        int idx = tid + j * 256;               // 0..1023
        int r = idx >> 4, cc = (idx & 15) * 4;
        cp_async16(kbuf_b[0] + (uint32_t)(r * KP + cc) * 4u,
                   Kg + bh + (size_t)r * CC + cc);
        cp_async16(vbuf_b[0] + (uint32_t)(r * KP + cc) * 4u,
                   vtp + (size_t)r * TT + cc);
    }
    asm volatile("cp.async.commit_group;");
    asm volatile("cp.async.wait_group 0;");
    __syncthreads();

    for (int t = 0; t < ntiles; t++) {
        const int buf = t & 1;
        if (t + 1 < ntiles) {
            const int kv0n = (t + 1) * AKV;
            #pragma unroll
            for (int j = 0; j < 4; j++) {
                int idx = tid + j * 256;
                int r = idx >> 4, cc = (idx & 15) * 4;
                cp_async16(kbuf_b[buf ^ 1] + (uint32_t)(r * KP + cc) * 4u,
                           Kg + bh + (size_t)(kv0n + r) * CC + cc);
                cp_async16(vbuf_b[buf ^ 1] + (uint32_t)(r * KP + cc) * 4u,
                           vtp + (size_t)r * TT + kv0n + cc);
            }
            asm volatile("cp.async.commit_group;");
        }

        const int kv0 = t * AKV;
        if (kv0 <= wrow_last) {   // warp has at least one unmasked element
            const uint32_t kB = kLd[buf];
            const uint32_t vB = vLd[buf];
            // ---- S = Q K^T (K fragments via ldmatrix.x4) ----
            #pragma unroll
            for (int nt = 0; nt < 8; nt++) {
                s[nt][0] = s[nt][1] = s[nt][2] = s[nt][3] = 0.f;
            }
            #pragma unroll
            for (int nt = 0; nt < 8; nt++) {
                #pragma unroll
                for (int kkp = 0; kkp < 4; kkp++) {
                    uint32_t kb[4];
                    ldsm_x4(kb[0], kb[1], kb[2], kb[3],
                            kB + (uint32_t)((nt * 8 * KP + kkp * 16) * 4));
                    mma_tf32(s[nt], qa[2 * kkp],     &kb[0]);
                    mma_tf32(s[nt], qa[2 * kkp + 1], &kb[2]);
                }
            }
            // ---- causal mask (diagonal tiles only) ----
            if (kv0 + AKV - 1 > wrow_first) {
                const int r0a = wrow_first + g, r1a = r0a + 8;
                #pragma unroll
                for (int nt = 0; nt < 8; nt++) {
                    const int c = kv0 + nt * 8 + 2 * tg;
                    if (c     > r0a) s[nt][0] = -1e30f;
                    if (c + 1 > r0a) s[nt][1] = -1e30f;
                    if (c     > r1a) s[nt][2] = -1e30f;
                    if (c + 1 > r1a) s[nt][3] = -1e30f;
                }
            }
            // ---- online softmax (register-resident) ----
            float mx0 = m0, mx1 = m1;
            #pragma unroll
            for (int nt = 0; nt < 8; nt++) {
                mx0 = fmaxf(mx0, fmaxf(s[nt][0], s[nt][1]));
                mx1 = fmaxf(mx1, fmaxf(s[nt][2], s[nt][3]));
            }
            mx0 = fmaxf(mx0, __shfl_xor_sync(0xffffffffu, mx0, 1));
            mx0 = fmaxf(mx0, __shfl_xor_sync(0xffffffffu, mx0, 2));
            mx1 = fmaxf(mx1, __shfl_xor_sync(0xffffffffu, mx1, 1));
            mx1 = fmaxf(mx1, __shfl_xor_sync(0xffffffffu, mx1, 2));
            const float al0 = __expf(m0 - mx0), al1 = __expf(m1 - mx1);
            m0 = mx0; m1 = mx1;
            float sum0 = 0.f, sum1 = 0.f;
            #pragma unroll
            for (int nt = 0; nt < 8; nt++) {
                s[nt][0] = __expf(s[nt][0] - mx0); sum0 += s[nt][0];
                s[nt][1] = __expf(s[nt][1] - mx0); sum0 += s[nt][1];
                s[nt][2] = __expf(s[nt][2] - mx1); sum1 += s[nt][2];
                s[nt][3] = __expf(s[nt][3] - mx1); sum1 += s[nt][3];
            }
            l0 = l0 * al0 + sum0;
            l1 = l1 * al1 + sum1;
            #pragma unroll
            for (int nt = 0; nt < 8; nt++) {
                oo[nt][0] *= al0; oo[nt][1] *= al0;
                oo[nt][2] *= al1; oo[nt][3] *= al1;
            }
            // ---- P (C-frag) -> A-frag via shuffles, in place ----
            const int base = lane & ~3;
            #pragma unroll
            for (int kk = 0; kk < 8; kk++) {
                const int srcA = base | (tg >> 1);
                const int srcB = srcA + 2;
                float x0 = __shfl_sync(0xffffffffu, s[kk][0], srcA);
                float x1 = __shfl_sync(0xffffffffu, s[kk][1], srcA);
                float x2 = __shfl_sync(0xffffffffu, s[kk][2], srcA);
                float x3 = __shfl_sync(0xffffffffu, s[kk][3], srcA);
                float y0 = __shfl_sync(0xffffffffu, s[kk][0], srcB);
                float y1 = __shfl_sync(0xffffffffu, s[kk][1], srcB);
                float y2 = __shfl_sync(0xffffffffu, s[kk][2], srcB);
                float y3 = __shfl_sync(0xffffffffu, s[kk][3], srcB);
                const bool odd = tg & 1;
                s[kk][0] = odd ? x1 : x0;   // a0: row g,   col tg
                s[kk][1] = odd ? x3 : x2;   // a1: row g+8, col tg
                s[kk][2] = odd ? y1 : y0;   // a2: row g,   col tg+4
                s[kk][3] = odd ? y3 : y2;   // a3: row g+8, col tg+4
            }
            // ---- O += P V  (V fragments via ldmatrix.x4 on V^T) ----
            #pragma unroll
            for (int nt = 0; nt < 8; nt++) {
                #pragma unroll
                for (int kkp = 0; kkp < 4; kkp++) {
                    uint32_t vb[4];
                    ldsm_x4(vb[0], vb[1], vb[2], vb[3],
                            vB + (uint32_t)((nt * 8 * KP + kkp * 16) * 4));
                    mma_tf32(oo[nt], reinterpret_cast<uint32_t*>(s[2 * kkp]),
                             &vb[0]);
                    mma_tf32(oo[nt], reinterpret_cast<uint32_t*>(s[2 * kkp + 1]),
                             &vb[2]);
                }
            }
        }
        if (t + 1 < ntiles) asm volatile("cp.async.wait_group 0;");
        __syncthreads();
    }

    // ---- finalize: reduce l over the quad, normalize, store ----
    l0 += __shfl_xor_sync(0xffffffffu, l0, 1);
    l0 += __shfl_xor_sync(0xffffffffu, l0, 2);
    l1 += __shfl_xor_sync(0xffffffffu, l1, 1);
    l1 += __shfl_xor_sync(0xffffffffu, l1, 2);
    const float inv0 = 1.f / l0, inv1 = 1.f / l1;
    const int r0a = q0 + w * 16 + g, r1a = r0a + 8;
    #pragma unroll
    for (int nt = 0; nt < 8; nt++) {
        const int c = nt * 8 + 2 * tg;
        *reinterpret_cast<float2*>(Og + bh + (size_t)r0a * CC + c) =
            make_float2(oo[nt][0] * inv0, oo[nt][1] * inv0);
        *reinterpret_cast<float2*>(Og + bh + (size_t)r1a * CC + c) =
            make_float2(oo[nt][2] * inv1, oo[nt][3] * inv1);
    }
}

// ---------------------------------------------------------------------------
// Launch
// ---------------------------------------------------------------------------
extern "C" void kernel_launch(void* const* d_in, const int* in_sizes, int n_in,
                              void* d_out, int out_size)
{
    const float* x  = (const float*)d_in[0];
    const float* Wq = (const float*)d_in[1];
    const float* bq = (const float*)d_in[2];
    const float* Wk = (const float*)d_in[3];
    const float* bk = (const float*)d_in[4];
    const float* Wv = (const float*)d_in[5];
    const float* bv = (const float*)d_in[6];
    const float* Wo = (const float*)d_in[7];
    const float* bo = (const float*)d_in[8];
    float* out = (float*)d_out;

    float *qp, *kp, *vp, *ap;
    cudaGetSymbolAddress((void**)&qp, g_q);
    cudaGetSymbolAddress((void**)&kp, g_k);
    cudaGetSymbolAddress((void**)&vp, g_v);
    cudaGetSymbolAddress((void**)&ap, g_att);

    cudaFuncSetAttribute(gemm_qkv_kernel,
                         cudaFuncAttributeMaxDynamicSharedMemorySize,
                         GEMM_SMEM_BYTES);
    cudaFuncSetAttribute(gemm_mma_kernel,
                         cudaFuncAttributeMaxDynamicSharedMemorySize,
                         GEMM_SMEM_BYTES);

    // Fused QKV projection: one launch, 768 CTAs (V written transposed)
    gemm_qkv_kernel<<<dim3(CC / 128, MM / 128, 3), 256, GEMM_SMEM_BYTES>>>(
        x, Wq, bq, qp, Wk, bk, kp, Wv, bv, vp);

    cudaFuncSetAttribute(attention_mma_kernel,
                         cudaFuncAttributeMaxDynamicSharedMemorySize,
                         ATT_SMEM_BYTES);
    attention_mma_kernel<<<dim3(TT / AQ, HH, BB), 256, ATT_SMEM_BYTES>>>(
        qp, kp, vp, ap);

    gemm_mma_kernel<<<dim3(CC / 128, MM / 128), 256, GEMM_SMEM_BYTES>>>(
        ap, Wo, bo, out);
}

// round 16
// speedup vs baseline: 1.3246x; 1.3115x over previous
#include <cuda_runtime.h>
#include <cuda_bf16.h>
#include <cuda_fp16.h>
#include <math.h>
#include <cstdint>

// Problem constants
#define BB 2
#define TT 2048
#define CC 1024
#define HH 16
#define DD 64
#define MM (BB*TT)   // 4096

// ---------------------------------------------------------------------------
// Scratch (allocation-free: __device__ globals)
// ---------------------------------------------------------------------------
__device__ float  g_q[MM*CC];
__device__ float  g_k[MM*CC];
__device__ float  g_v[MM*CC];
__device__ __half g_atth[MM*CC];     // attention output, fp16 for out-proj
__device__ __half g_xh[MM*CC];       // fp16 copies (prepass)
__device__ __half g_wqh[CC*CC];
__device__ __half g_wkh[CC*CC];
__device__ __half g_wvh[CC*CC];
__device__ __half g_woh[CC*CC];

// ---------------------------------------------------------------------------
// mma.sync helpers (sm_100 base target: HMMA path, no tcgen05)
// ---------------------------------------------------------------------------
__device__ __forceinline__ void mma_tf32(float* d, const uint32_t* a, const uint32_t* b) {
    asm volatile(
        "mma.sync.aligned.m16n8k8.row.col.f32.tf32.tf32.f32 "
        "{%0,%1,%2,%3}, {%4,%5,%6,%7}, {%8,%9}, {%0,%1,%2,%3};"
        : "+f"(d[0]), "+f"(d[1]), "+f"(d[2]), "+f"(d[3])
        : "r"(a[0]), "r"(a[1]), "r"(a[2]), "r"(a[3]),
          "r"(b[0]), "r"(b[1]));
}

__device__ __forceinline__ void mma_f16(float* d, const uint32_t* a, const uint32_t* b) {
    asm volatile(
        "mma.sync.aligned.m16n8k16.row.col.f32.f16.f16.f32 "
        "{%0,%1,%2,%3}, {%4,%5,%6,%7}, {%8,%9}, {%0,%1,%2,%3};"
        : "+f"(d[0]), "+f"(d[1]), "+f"(d[2]), "+f"(d[3])
        : "r"(a[0]), "r"(a[1]), "r"(a[2]), "r"(a[3]),
          "r"(b[0]), "r"(b[1]));
}

// ldmatrix: four 8x8 b16 tiles.
__device__ __forceinline__ void ldsm_x4(uint32_t& r0, uint32_t& r1,
                                        uint32_t& r2, uint32_t& r3,
                                        uint32_t addr) {
    asm volatile(
        "ldmatrix.sync.aligned.m8n8.x4.shared.b16 {%0,%1,%2,%3}, [%4];"
        : "=r"(r0), "=r"(r1), "=r"(r2), "=r"(r3) : "r"(addr));
}

__device__ __forceinline__ uint32_t smem_u32(const void* p) {
    uint32_t a;
    asm("{ .reg .u64 t; cvta.to.shared.u64 t, %1; cvt.u32.u64 %0, t; }"
        : "=r"(a) : "l"(p));
    return a;
}

__device__ __forceinline__ void cp_async16(uint32_t dst, const void* src) {
    asm volatile("cp.async.ca.shared.global [%0], [%1], 16;" :: "r"(dst), "l"(src));
}

__device__ __forceinline__ void cp_async16_cg(uint32_t dst, const void* src) {
    asm volatile("cp.async.cg.shared.global [%0], [%1], 16;" :: "r"(dst), "l"(src));
}

// ===========================================================================
// Prepass: fp32 -> fp16 conversion (x once, 4 weights fused in one launch)
// ===========================================================================
__global__ __launch_bounds__(256) void f32_to_f16_kernel(
    const float4* __restrict__ src, uint2* __restrict__ dst, int n4)
{
    int i = blockIdx.x * blockDim.x + threadIdx.x;
    if (i < n4) {
        float4 v = src[i];
        __half2 h0 = __floats2half2_rn(v.x, v.y);
        __half2 h1 = __floats2half2_rn(v.z, v.w);
        uint2 o;
        o.x = *reinterpret_cast<uint32_t*>(&h0);
        o.y = *reinterpret_cast<uint32_t*>(&h1);
        dst[i] = o;
    }
}

__global__ __launch_bounds__(256) void w4_to_f16_kernel(
    const float4* __restrict__ w0, const float4* __restrict__ w1,
    const float4* __restrict__ w2, const float4* __restrict__ w3,
    uint2* __restrict__ d0, uint2* __restrict__ d1,
    uint2* __restrict__ d2, uint2* __restrict__ d3, int n4)
{
    const float4* s; uint2* d;
    if (blockIdx.y == 0)      { s = w0; d = d0; }
    else if (blockIdx.y == 1) { s = w1; d = d1; }
    else if (blockIdx.y == 2) { s = w2; d = d2; }
    else                      { s = w3; d = d3; }
    int i = blockIdx.x * blockDim.x + threadIdx.x;
    if (i < n4) {
        float4 v = s[i];
        __half2 h0 = __floats2half2_rn(v.x, v.y);
        __half2 h1 = __floats2half2_rn(v.z, v.w);
        uint2 o;
        o.x = *reinterpret_cast<uint32_t*>(&h0);
        o.y = *reinterpret_cast<uint32_t*>(&h1);
        d[i] = o;
    }
}

// ===========================================================================
// fp16 mma.sync GEMM core:  C[M,N] = A[M,K] @ W[N,K]^T + bias[N]  (fp32 out)
// CTA tile 128x128, k-tile = 32 halves (64B rows), 8 warps (2M x 4N),
// warp tile 64x32, m16n8k16. 4-stage cp.async ring, unrolled by 4
// (constant stage indices). Fragments via ldmatrix.x4 (native b16).
// ===========================================================================
#define KT 32               // halves per k-tile
#define BKH 40              // padded row stride in halves (80 B)
#define NKT (CC / KT)       // 32  (divisible by 4)
#define GSTG 4
#define STG_B (128 * BKH * 2)                      // bytes per array per stage
#define GEMM_SMEM_BYTES (GSTG * 2 * STG_B)         // 81920

__device__ __forceinline__ void gemm_mma_body(
    const __half* __restrict__ A, const __half* __restrict__ W,
    const float* __restrict__ bias, float* __restrict__ C,
    int m0, int n0, uint32_t* sm)
{
    const int tid = threadIdx.x;
    const int wid = tid >> 5;
    const int lane = tid & 31;
    const int g  = lane >> 2;
    const int tg = lane & 3;
    const int warp_m = wid >> 2;
    const int warp_n = wid & 3;
    const __half* Ag = A + (size_t)m0 * CC;
    const __half* Wg = W + (size_t)n0 * CC;

    const uint32_t sbase = smem_u32(sm);

    // ldmatrix per-lane selectors (byte offsets within a 16x16 half tile)
    const int arow = (lane & 7) + ((lane >> 3) & 1) * 8;   // A: m-row
    const int acolB = (lane >> 4) * 16;                    // A: k byte offset
    const int brow = (lane & 7) + ((lane >> 4) & 1) * 8;   // B: n-row
    const int bcolB = ((lane >> 3) & 1) * 16;              // B: k byte offset

    uint32_t aLd[GSTG], bLd[GSTG];
    #pragma unroll
    for (int s = 0; s < GSTG; s++) {
        aLd[s] = sbase + (uint32_t)(s * STG_B)
               + (uint32_t)((warp_m * 64 + arow) * BKH * 2 + acolB);
        bLd[s] = sbase + (uint32_t)((GSTG + s) * STG_B)
               + (uint32_t)((warp_n * 32 + brow) * BKH * 2 + bcolB);
    }

    float d[4][4][4];
    #pragma unroll
    for (int mt = 0; mt < 4; mt++)
        #pragma unroll
        for (int nt = 0; nt < 4; nt++)
            #pragma unroll
            for (int r = 0; r < 4; r++) d[mt][nt][r] = 0.f;

    const int r0 = tid >> 2;          // 0..63 : rows r0 and r0+64
    const int c0h = (tid & 3) * 8;    // half index 0,8,16,24 (16B segments)
    const uint32_t so0 = (uint32_t)(r0 * BKH + c0h) * 2u;
    const uint32_t so1 = (uint32_t)((r0 + 64) * BKH + c0h) * 2u;

    // preload tiles 0,1,2 into stages 0,1,2
    #pragma unroll
    for (int p = 0; p < 3; p++) {
        const int koff = p * KT;
        const uint32_t aB = sbase + (uint32_t)(p * STG_B);
        const uint32_t wB = sbase + (uint32_t)((GSTG + p) * STG_B);
        cp_async16_cg(aB + so0, Ag + (size_t)r0 * CC + koff + c0h);
        cp_async16_cg(aB + so1, Ag + (size_t)(r0 + 64) * CC + koff + c0h);
        cp_async16_cg(wB + so0, Wg + (size_t)r0 * CC + koff + c0h);
        cp_async16_cg(wB + so1, Wg + (size_t)(r0 + 64) * CC + koff + c0h);
        asm volatile("cp.async.commit_group;");
    }

    for (int kt = 0; kt < NKT; kt += GSTG) {
        #pragma unroll
        for (int u = 0; u < GSTG; u++) {
            asm volatile("cp.async.wait_group 2;");
            __syncthreads();

            const int pf = kt + u + 3;
            if (pf < NKT) {
                const int ps = (u + 3) & 3;          // compile-time constant
                const int koff = pf * KT;
                const uint32_t aB = sbase + (uint32_t)(ps * STG_B);
                const uint32_t wB = sbase + (uint32_t)((GSTG + ps) * STG_B);
                cp_async16_cg(aB + so0, Ag + (size_t)r0 * CC + koff + c0h);
                cp_async16_cg(aB + so1, Ag + (size_t)(r0 + 64) * CC + koff + c0h);
                cp_async16_cg(wB + so0, Wg + (size_t)r0 * CC + koff + c0h);
                cp_async16_cg(wB + so1, Wg + (size_t)(r0 + 64) * CC + koff + c0h);
            }
            asm volatile("cp.async.commit_group;");  // uniform group count

            const uint32_t aB = aLd[u];              // constant index
            const uint32_t bB = bLd[u];
            #pragma unroll
            for (int ks = 0; ks < 2; ks++) {         // 2 k-steps of k=16
                uint32_t af[4][4], bf[2][4];
                #pragma unroll
                for (int mt = 0; mt < 4; mt++) {
                    ldsm_x4(af[mt][0], af[mt][1], af[mt][2], af[mt][3],
                            aB + (uint32_t)(mt * 16 * BKH * 2 + ks * 32));
                }
                #pragma unroll
                for (int np = 0; np < 2; np++) {
                    ldsm_x4(bf[np][0], bf[np][1], bf[np][2], bf[np][3],
                            bB + (uint32_t)(np * 16 * BKH * 2 + ks * 32));
                }
                #pragma unroll
                for (int mt = 0; mt < 4; mt++)
                    #pragma unroll
                    for (int nt = 0; nt < 4; nt++)
                        mma_f16(d[mt][nt], af[mt], &bf[nt >> 1][(nt & 1) * 2]);
            }
        }
    }

    #pragma unroll
    for (int mt = 0; mt < 4; mt++) {
        const int row = m0 + warp_m * 64 + mt * 16 + g;
        #pragma unroll
        for (int nt = 0; nt < 4; nt++) {
            const int col = n0 + warp_n * 32 + nt * 8 + tg * 2;
            float2 bv = *reinterpret_cast<const float2*>(bias + col);
            float2 o0 = make_float2(d[mt][nt][0] + bv.x, d[mt][nt][1] + bv.y);
            float2 o1 = make_float2(d[mt][nt][2] + bv.x, d[mt][nt][3] + bv.y);
            *reinterpret_cast<float2*>(C + (size_t)row * CC + col) = o0;
            *reinterpret_cast<float2*>(C + (size_t)(row + 8) * CC + col) = o1;
        }
    }
}

// Single-matrix GEMM (output projection; A fp16, W fp16, C fp32)
__global__ __launch_bounds__(256) void gemm_mma_kernel(
    const __half* __restrict__ A, const __half* __restrict__ W,
    const float* __restrict__ bias, float* __restrict__ C)
{
    extern __shared__ __align__(16) uint32_t smg[];
    gemm_mma_body(A, W, bias, C, blockIdx.y * 128, blockIdx.x * 128, smg);
}

// Fused QKV projection: blockIdx.z selects {Wq,bq,q} / {Wk,bk,k} / {Wv,bv,v}
__global__ __launch_bounds__(256) void gemm_qkv_kernel(
    const __half* __restrict__ x,
    const __half* __restrict__ Wq, const float* __restrict__ bq, float* __restrict__ q,
    const __half* __restrict__ Wk, const float* __restrict__ bk, float* __restrict__ k,
    const __half* __restrict__ Wv, const float* __restrict__ bv, float* __restrict__ v)
{
    extern __shared__ __align__(16) uint32_t smg[];
    const __half* W; const float* b; float* C;
    if (blockIdx.z == 0)      { W = Wq; b = bq; C = q; }
    else if (blockIdx.z == 1) { W = Wk; b = bk; C = k; }
    else                      { W = Wv; b = bv; C = v; }
    gemm_mma_body(x, W, b, C, blockIdx.y * 128, blockIdx.x * 128, smg);
}

// ===========================================================================
// Tensor-core flash attention (causal), tf32 mma.sync.  (R12 version;
// only change: output written fp16 to feed the fp16 out-projection.)
// CTA: 128 q rows, 8 warps (16 q rows/warp), kv tile 64, D=64.
// grid = (T/128, H, B) = (16, 16, 2), 256 threads.
// K fragments via ldmatrix.x4; V scalar. qt REVERSED (heavy blocks first).
// ===========================================================================
#define AQ 128
#define AKV 64
#define KP 68               // K/Q smem row pad (floats): conflict-free
#define VP 72               // V   smem row pad (floats): conflict-free
#define SM_K0 0
#define SM_K1 (64*KP)
#define SM_V0 (2*64*KP)
#define SM_V1 (2*64*KP + 64*VP)
#define ATT_SMEM_BYTES ((2*64*KP + 2*64*VP) * 4)   // 71680

__global__ __launch_bounds__(256, 2) void attention_mma_kernel(
    const float* __restrict__ Qg, const float* __restrict__ Kg,
    const float* __restrict__ Vg, __half* __restrict__ Og)
{
    extern __shared__ __align__(16) float smf[];
    const uint32_t sbase = smem_u32(smf);
    const int tid = threadIdx.x;
    const int w = tid >> 5;
    const int lane = tid & 31;
    const int g = lane >> 2, tg = lane & 3;
    const int qt = gridDim.x - 1 - blockIdx.x;   // heavy blocks first
    const int h = blockIdx.y, b = blockIdx.z;
    const int q0 = qt * AQ;
    const size_t bh = (size_t)b * TT * CC + (size_t)h * DD;  // + t*CC + d

    // --- stage Q (scaled by 1/sqrt(D)) into smem [128][KP] ---
    {
        const float sc = 0.125f;
        #pragma unroll
        for (int j = 0; j < 8; j++) {
            int idx = tid + j * 256;           // 0..2047
            int r = idx >> 4, cc = (idx & 15) * 4;
            float4 val = *reinterpret_cast<const float4*>(
                Qg + bh + (size_t)(q0 + r) * CC + cc);
            float* dst = smf + r * KP + cc;
            dst[0] = val.x * sc; dst[1] = val.y * sc;
            dst[2] = val.z * sc; dst[3] = val.w * sc;
        }
    }
    __syncthreads();

    // --- Q A-fragments to registers (persist whole kernel) ---
    uint32_t qa[8][4];
    {
        const uint32_t* Qs = reinterpret_cast<const uint32_t*>(smf);
        const int r0 = (w * 16 + g) * KP;
        #pragma unroll
        for (int kk = 0; kk < 8; kk++) {
            qa[kk][0] = Qs[r0 + kk * 8 + tg];
            qa[kk][1] = Qs[r0 + 8 * KP + kk * 8 + tg];
            qa[kk][2] = Qs[r0 + kk * 8 + tg + 4];
            qa[kk][3] = Qs[r0 + 8 * KP + kk * 8 + tg + 4];
        }
    }
    __syncthreads();   // Q stage area becomes K buffers

    float s[8][4], oo[8][4];
    float m0 = -1e30f, m1 = -1e30f, l0 = 0.f, l1 = 0.f;
    #pragma unroll
    for (int nt = 0; nt < 8; nt++) {
        oo[nt][0] = oo[nt][1] = oo[nt][2] = oo[nt][3] = 0.f;
    }

    const int ntiles = 2 * qt + 2;
    const int wrow_first = q0 + w * 16;
    const int wrow_last  = wrow_first + 15;

    const uint32_t kbuf_b[2] = { sbase + SM_K0 * 4u, sbase + SM_K1 * 4u };
    const uint32_t vbuf_b[2] = { sbase + SM_V0 * 4u, sbase + SM_V1 * 4u };

    // K ldmatrix per-lane selectors
    const int krow = lane & 7;
    const int kcol = (lane >> 3) * 4;
    const uint32_t kLd[2] = {
        kbuf_b[0] + (uint32_t)((krow * KP + kcol) * 4),
        kbuf_b[1] + (uint32_t)((krow * KP + kcol) * 4)
    };

    // preload tile 0
    #pragma unroll
    for (int j = 0; j < 4; j++) {
        int idx = tid + j * 256;               // 0..1023
        int r = idx >> 4, cc = (idx & 15) * 4;
        const float* srcK = Kg + bh + (size_t)r * CC + cc;
        const float* srcV = Vg + bh + (size_t)r * CC + cc;
        cp_async16(kbuf_b[0] + (uint32_t)(r * KP + cc) * 4u, srcK);
        cp_async16(vbuf_b[0] + (uint32_t)(r * VP + cc) * 4u, srcV);
    }
    asm volatile("cp.async.commit_group;");
    asm volatile("cp.async.wait_group 0;");
    __syncthreads();

    for (int t = 0; t < ntiles; t++) {
        const int buf = t & 1;
        if (t + 1 < ntiles) {
            const int kv0n = (t + 1) * AKV;
            #pragma unroll
            for (int j = 0; j < 4; j++) {
                int idx = tid + j * 256;
                int r = idx >> 4, cc = (idx & 15) * 4;
                const float* srcK = Kg + bh + (size_t)(kv0n + r) * CC + cc;
                const float* srcV = Vg + bh + (size_t)(kv0n + r) * CC + cc;
                cp_async16(kbuf_b[buf ^ 1] + (uint32_t)(r * KP + cc) * 4u, srcK);
                cp_async16(vbuf_b[buf ^ 1] + (uint32_t)(r * VP + cc) * 4u, srcV);
            }
            asm volatile("cp.async.commit_group;");
        }

        const int kv0 = t * AKV;
        if (kv0 <= wrow_last) {   // warp has at least one unmasked element
            const uint32_t kB = kLd[buf];
            const uint32_t* Vs = reinterpret_cast<const uint32_t*>(smf)
                                 + (buf ? SM_V1 : SM_V0);
            // ---- S = Q K^T (K fragments via ldmatrix.x4) ----
            #pragma unroll
            for (int nt = 0; nt < 8; nt++) {
                s[nt][0] = s[nt][1] = s[nt][2] = s[nt][3] = 0.f;
            }
            #pragma unroll
            for (int nt = 0; nt < 8; nt++) {
                #pragma unroll
                for (int kkp = 0; kkp < 4; kkp++) {
                    uint32_t kb[4];
                    ldsm_x4(kb[0], kb[1], kb[2], kb[3],
                            kB + (uint32_t)((nt * 8 * KP + kkp * 16) * 4));
                    mma_tf32(s[nt], qa[2 * kkp],     &kb[0]);
                    mma_tf32(s[nt], qa[2 * kkp + 1], &kb[2]);
                }
            }
            // ---- causal mask (diagonal tiles only) ----
            if (kv0 + AKV - 1 > wrow_first) {
                const int r0a = wrow_first + g, r1a = r0a + 8;
                #pragma unroll
                for (int nt = 0; nt < 8; nt++) {
                    const int c = kv0 + nt * 8 + 2 * tg;
                    if (c     > r0a) s[nt][0] = -1e30f;
                    if (c + 1 > r0a) s[nt][1] = -1e30f;
                    if (c     > r1a) s[nt][2] = -1e30f;
                    if (c + 1 > r1a) s[nt][3] = -1e30f;
                }
            }
            // ---- online softmax (register-resident) ----
            float mx0 = m0, mx1 = m1;
            #pragma unroll
            for (int nt = 0; nt < 8; nt++) {
                mx0 = fmaxf(mx0, fmaxf(s[nt][0], s[nt][1]));
                mx1 = fmaxf(mx1, fmaxf(s[nt][2], s[nt][3]));
            }
            mx0 = fmaxf(mx0, __shfl_xor_sync(0xffffffffu, mx0, 1));
            mx0 = fmaxf(mx0, __shfl_xor_sync(0xffffffffu, mx0, 2));
            mx1 = fmaxf(mx1, __shfl_xor_sync(0xffffffffu, mx1, 1));
            mx1 = fmaxf(mx1, __shfl_xor_sync(0xffffffffu, mx1, 2));
            const float al0 = __expf(m0 - mx0), al1 = __expf(m1 - mx1);
            m0 = mx0; m1 = mx1;
            float sum0 = 0.f, sum1 = 0.f;
            #pragma unroll
            for (int nt = 0; nt < 8; nt++) {
                s[nt][0] = __expf(s[nt][0] - mx0); sum0 += s[nt][0];
                s[nt][1] = __expf(s[nt][1] - mx0); sum0 += s[nt][1];
                s[nt][2] = __expf(s[nt][2] - mx1); sum1 += s[nt][2];
                s[nt][3] = __expf(s[nt][3] - mx1); sum1 += s[nt][3];
            }
            l0 = l0 * al0 + sum0;
            l1 = l1 * al1 + sum1;
            #pragma unroll
            for (int nt = 0; nt < 8; nt++) {
                oo[nt][0] *= al0; oo[nt][1] *= al0;
                oo[nt][2] *= al1; oo[nt][3] *= al1;
            }
            // ---- P (C-frag) -> A-frag via shuffles, in place ----
            const int base = lane & ~3;
            #pragma unroll
            for (int kk = 0; kk < 8; kk++) {
                const int srcA = base | (tg >> 1);
                const int srcB = srcA + 2;
                float x0 = __shfl_sync(0xffffffffu, s[kk][0], srcA);
                float x1 = __shfl_sync(0xffffffffu, s[kk][1], srcA);
                float x2 = __shfl_sync(0xffffffffu, s[kk][2], srcA);
                float x3 = __shfl_sync(0xffffffffu, s[kk][3], srcA);
                float y0 = __shfl_sync(0xffffffffu, s[kk][0], srcB);
                float y1 = __shfl_sync(0xffffffffu, s[kk][1], srcB);
                float y2 = __shfl_sync(0xffffffffu, s[kk][2], srcB);
                float y3 = __shfl_sync(0xffffffffu, s[kk][3], srcB);
                const bool odd = tg & 1;
                s[kk][0] = odd ? x1 : x0;   // a0: row g,   col tg
                s[kk][1] = odd ? x3 : x2;   // a1: row g+8, col tg
                s[kk][2] = odd ? y1 : y0;   // a2: row g,   col tg+4
                s[kk][3] = odd ? y3 : y2;   // a3: row g+8, col tg+4
            }
            // ---- O += P V ----
            #pragma unroll
            for (int nt = 0; nt < 8; nt++) {
                #pragma unroll
                for (int kk = 0; kk < 8; kk++) {
                    uint32_t bb[2] = { Vs[(kk * 8 + tg) * VP + nt * 8 + g],
                                       Vs[(kk * 8 + tg + 4) * VP + nt * 8 + g] };
                    mma_tf32(oo[nt], reinterpret_cast<uint32_t*>(s[kk]), bb);
                }
            }
        }
        if (t + 1 < ntiles) asm volatile("cp.async.wait_group 0;");
        __syncthreads();
    }

    // ---- finalize: reduce l over the quad, normalize, store fp16 ----
    l0 += __shfl_xor_sync(0xffffffffu, l0, 1);
    l0 += __shfl_xor_sync(0xffffffffu, l0, 2);
    l1 += __shfl_xor_sync(0xffffffffu, l1, 1);
    l1 += __shfl_xor_sync(0xffffffffu, l1, 2);
    const float inv0 = 1.f / l0, inv1 = 1.f / l1;
    const int r0a = q0 + w * 16 + g, r1a = r0a + 8;
    #pragma unroll
    for (int nt = 0; nt < 8; nt++) {
        const int c = nt * 8 + 2 * tg;
        *reinterpret_cast<__half2*>(Og + bh + (size_t)r0a * CC + c) =
            __floats2half2_rn(oo[nt][0] * inv0, oo[nt][1] * inv0);
        *reinterpret_cast<__half2*>(Og + bh + (size_t)r1a * CC + c) =
            __floats2half2_rn(oo[nt][2] * inv1, oo[nt][3] * inv1);
    }
}

// ---------------------------------------------------------------------------
// Launch
// ---------------------------------------------------------------------------
extern "C" void kernel_launch(void* const* d_in, const int* in_sizes, int n_in,
                              void* d_out, int out_size)
{
    const float* x  = (const float*)d_in[0];
    const float* Wq = (const float*)d_in[1];
    const float* bq = (const float*)d_in[2];
    const float* Wk = (const float*)d_in[3];
    const float* bk = (const float*)d_in[4];
    const float* Wv = (const float*)d_in[5];
    const float* bv = (const float*)d_in[6];
    const float* Wo = (const float*)d_in[7];
    const float* bo = (const float*)d_in[8];
    float* out = (float*)d_out;

    float *qp, *kp, *vp;
    __half *ath, *xh, *wqh, *wkh, *wvh, *woh;
    cudaGetSymbolAddress((void**)&qp, g_q);
    cudaGetSymbolAddress((void**)&kp, g_k);
    cudaGetSymbolAddress((void**)&vp, g_v);
    cudaGetSymbolAddress((void**)&ath, g_atth);
    cudaGetSymbolAddress((void**)&xh, g_xh);
    cudaGetSymbolAddress((void**)&wqh, g_wqh);
    cudaGetSymbolAddress((void**)&wkh, g_wkh);
    cudaGetSymbolAddress((void**)&wvh, g_wvh);
    cudaGetSymbolAddress((void**)&woh, g_woh);

    cudaFuncSetAttribute(gemm_qkv_kernel,
                         cudaFuncAttributeMaxDynamicSharedMemorySize,
                         GEMM_SMEM_BYTES);
    cudaFuncSetAttribute(gemm_mma_kernel,
                         cudaFuncAttributeMaxDynamicSharedMemorySize,
                         GEMM_SMEM_BYTES);

    // Prepass: fp32 -> fp16 (x, then 4 weights in one fused launch)
    const int nx4 = MM * CC / 4;   // 1,048,576
    const int nw4 = CC * CC / 4;   // 262,144
    f32_to_f16_kernel<<<(nx4 + 255) / 256, 256>>>(
        (const float4*)x, (uint2*)xh, nx4);
    w4_to_f16_kernel<<<dim3((nw4 + 255) / 256, 4), 256>>>(
        (const float4*)Wq, (const float4*)Wk, (const float4*)Wv,
        (const float4*)Wo,
        (uint2*)wqh, (uint2*)wkh, (uint2*)wvh, (uint2*)woh, nw4);

    // Fused QKV projection: one launch, 768 CTAs (fp16 in, fp32 out)
    gemm_qkv_kernel<<<dim3(CC / 128, MM / 128, 3), 256, GEMM_SMEM_BYTES>>>(
        xh, wqh, bq, qp, wkh, bk, kp, wvh, bv, vp);

    cudaFuncSetAttribute(attention_mma_kernel,
                         cudaFuncAttributeMaxDynamicSharedMemorySize,
                         ATT_SMEM_BYTES);
    attention_mma_kernel<<<dim3(TT / AQ, HH, BB), 256, ATT_SMEM_BYTES>>>(
        qp, kp, vp, ath);

    gemm_mma_kernel<<<dim3(CC / 128, MM / 128), 256, GEMM_SMEM_BYTES>>>(
        ath, woh, bo, out);
}